// round 8
// baseline (speedup 1.0000x reference)
#include <cuda_runtime.h>
#include <cstdint>

// Problem constants (fixed shapes per reference setup_inputs)
#define BQ   2048      // queries
#define NK   100000    // capacity
#define DIM  128       // key size
#define TOPK 50
#define DELTA 1e-3f

#define NPART 8
#define PARTK (NK / NPART)          // 12500
#define CANDM (NPART * TOPK)        // 400
#define MRG   512                   // merge sort width (>= CANDM, pow2)

// ---------------- scratch (static device globals; no runtime allocation) ----
__device__ float g_score[(size_t)BQ * NK];   // ~819 MB score matrix
__device__ float g_keynorm[NK];
__device__ float g_qnorm[BQ];
__device__ int   g_topk[BQ * TOPK];
__device__ float g_pv[BQ * NPART * TOPK];
__device__ int   g_pi[BQ * NPART * TOPK];

static __device__ __forceinline__ float finf() { return __int_as_float(0x7f800000); }

// ---------------- K0: row squared norms, XLA row-reduce replica -------------
// (FROZEN — this exact rounding/grouping is what makes selection match)
__global__ void norms_kernel(const float* __restrict__ src, int rows, int which) {
    int warp = (blockIdx.x * blockDim.x + threadIdx.x) >> 5;
    int lane = threadIdx.x & 31;
    if (warp >= rows) return;
    const float* r = src + (size_t)warp * DIM;
    float acc = 0.f;
#pragma unroll
    for (int pass = 0; pass < 2; pass++) {
        int base = pass * 64 + 2 * lane;
        float v0 = r[base];
        float v1 = r[base + 1];
        acc = __fadd_rn(acc, __fmul_rn(v0, v0));
        acc = __fadd_rn(acc, __fmul_rn(v1, v1));
    }
#pragma unroll
    for (int s = 16; s; s >>= 1)
        acc = __fadd_rn(acc, __shfl_xor_sync(0xffffffffu, acc, s));
    if (lane == 0) {
        if (which == 0) g_keynorm[warp] = acc;
        else            g_qnorm[warp]   = acc;
    }
}

// ---------------- K1: fp32 tiled GEMM -> scores (round-6 version, FROZEN) ---
// score[b][n] = (qnorm[b] - 2*dot(q_b,k_n)) + keynorm[n]
// dot: single accumulator per output, ascending k, FMA.
#define BM 64
#define BN 64
#define BKK 16
#define PADL 72

__global__ __launch_bounds__(256) void score_gemm(const float* __restrict__ Q,
                                                  const float* __restrict__ Kd) {
    __shared__ float As[BKK][PADL];
    __shared__ float Bs[BKK][PADL];

    int n0 = blockIdx.x * BN;
    int b0 = blockIdx.y * BM;
    int tid = threadIdx.x;
    int tx = tid & 15;
    int ty = tid >> 4;

    float acc[4][4];
#pragma unroll
    for (int i = 0; i < 4; i++)
#pragma unroll
        for (int j = 0; j < 4; j++) acc[i][j] = 0.f;

    int lr = tid >> 2;
    int lc = (tid & 3) * 4;

    for (int k0 = 0; k0 < DIM; k0 += BKK) {
        float4 a = *(const float4*)(Q + (size_t)(b0 + lr) * DIM + k0 + lc);
        int nrow = n0 + lr;
        float4 bv = make_float4(0.f, 0.f, 0.f, 0.f);
        if (nrow < NK)
            bv = *(const float4*)(Kd + (size_t)nrow * DIM + k0 + lc);

        __syncthreads();
        As[lc + 0][lr] = a.x;  As[lc + 1][lr] = a.y;
        As[lc + 2][lr] = a.z;  As[lc + 3][lr] = a.w;
        Bs[lc + 0][lr] = bv.x; Bs[lc + 1][lr] = bv.y;
        Bs[lc + 2][lr] = bv.z; Bs[lc + 3][lr] = bv.w;
        __syncthreads();

#pragma unroll
        for (int kk = 0; kk < BKK; kk++) {
            float4 av = *(const float4*)&As[kk][ty * 4];
            float4 bw = *(const float4*)&Bs[kk][tx * 4];
            float a_[4] = {av.x, av.y, av.z, av.w};
            float b_[4] = {bw.x, bw.y, bw.z, bw.w};
#pragma unroll
            for (int i = 0; i < 4; i++)
#pragma unroll
                for (int j = 0; j < 4; j++)
                    acc[i][j] = fmaf(a_[i], b_[j], acc[i][j]);   // ascending k
        }
    }

    int nbase = n0 + tx * 4;
    if (nbase + 3 < NK) {
        float kn[4];
#pragma unroll
        for (int j = 0; j < 4; j++) kn[j] = g_keynorm[nbase + j];
#pragma unroll
        for (int i = 0; i < 4; i++) {
            int bb = b0 + ty * 4 + i;
            float qn = g_qnorm[bb];
            float4 r;
            r.x = __fadd_rn(__fsub_rn(qn, 2.f * acc[i][0]), kn[0]);
            r.y = __fadd_rn(__fsub_rn(qn, 2.f * acc[i][1]), kn[1]);
            r.z = __fadd_rn(__fsub_rn(qn, 2.f * acc[i][2]), kn[2]);
            r.w = __fadd_rn(__fsub_rn(qn, 2.f * acc[i][3]), kn[3]);
            *(float4*)&g_score[(size_t)bb * NK + nbase] = r;
        }
    }
}

// ---------------- shared bitonic sort by (value, index) ascending -----------
template <int N>
static __device__ void sort_sh(float* sv, int* si, int tid) {
    for (int k = 2; k <= N; k <<= 1) {
        for (int j = k >> 1; j > 0; j >>= 1) {
            for (int i = tid; i < N; i += 256) {
                int ixj = i ^ j;
                if (ixj > i) {
                    float v1 = sv[i], v2 = sv[ixj];
                    int  i1 = si[i],  i2 = si[ixj];
                    bool up   = ((i & k) == 0);
                    bool less = (v1 < v2) || (v1 == v2 && i1 < i2);
                    if (less != up) {
                        sv[i] = v2; sv[ixj] = v1;
                        si[i] = i2; si[ixj] = i1;
                    }
                }
            }
            __syncthreads();
        }
    }
}

// ---------------- K2a: per-partition top-50 (deterministic scan-push) -------
#define POOL  2048
#define CHUNK 1024

__global__ __launch_bounds__(256) void topk_part() {
    int b    = blockIdx.x;
    int part = blockIdx.y;
    int tid  = threadIdx.x;
    int lane = tid & 31;
    int wid  = tid >> 5;
    const float* row = g_score + (size_t)b * NK + (size_t)part * PARTK;
    int gbase = part * PARTK;

    __shared__ float sv[POOL];
    __shared__ int   si[POOL];
    __shared__ int   s_cnt;
    __shared__ float s_tau;
    __shared__ int   s_wsum[8];
    __shared__ int   s_woff[8];
    __shared__ int   s_total;

    if (tid == 0) { s_cnt = 0; s_tau = finf(); }
    __syncthreads();

    const int nChunks = (PARTK + CHUNK - 1) / CHUNK;   // 13
    for (int c = 0; c < nChunks; c++) {
        int   base = c * CHUNK;
        float tau  = s_tau;

        float vals[4]; int idxs[4];
        int mycnt = 0;
        int i4 = base + tid * 4;
        if (i4 < PARTK) {   // PARTK % 4 == 0 => full float4 or nothing
            float4 v = *(const float4*)(row + i4);
            float vv[4] = {v.x, v.y, v.z, v.w};
#pragma unroll
            for (int e = 0; e < 4; e++) {
                if (vv[e] <= tau) { vals[mycnt] = vv[e]; idxs[mycnt] = gbase + i4 + e; mycnt++; }
            }
        }

        // deterministic block scan placement
        int scan = mycnt;
#pragma unroll
        for (int s = 1; s < 32; s <<= 1) {
            int t = __shfl_up_sync(0xffffffffu, scan, s);
            if (lane >= s) scan += t;
        }
        if (lane == 31) s_wsum[wid] = scan;
        __syncthreads();
        if (tid == 0) {
            int run = 0;
#pragma unroll
            for (int w = 0; w < 8; w++) { s_woff[w] = run; run += s_wsum[w]; }
            s_total = run;
        }
        __syncthreads();

        int pos = s_cnt + s_woff[wid] + (scan - mycnt);
        for (int k = 0; k < mycnt; k++) { sv[pos + k] = vals[k]; si[pos + k] = idxs[k]; }
        __syncthreads();
        if (tid == 0) s_cnt += s_total;
        __syncthreads();

        if (s_cnt > POOL - CHUNK) {
            int cnt = s_cnt;
            for (int i = tid; i < POOL; i += 256)
                if (i >= cnt) { sv[i] = finf(); si[i] = 0x7fffffff; }
            __syncthreads();
            sort_sh<POOL>(sv, si, tid);
            if (tid == 0) { s_cnt = TOPK; s_tau = sv[TOPK - 1]; }
            __syncthreads();
        }
    }

    {
        int cnt = s_cnt;
        for (int i = tid; i < POOL; i += 256)
            if (i >= cnt) { sv[i] = finf(); si[i] = 0x7fffffff; }
        __syncthreads();
        sort_sh<POOL>(sv, si, tid);
    }
    if (tid < TOPK) {
        int o = (b * NPART + part) * TOPK + tid;
        g_pv[o] = sv[tid];
        g_pi[o] = si[tid];
    }
}

// ---------------- K2b: merge 8x50 partition candidates -> global top-50 -----
__global__ __launch_bounds__(256) void topk_merge() {
    int b   = blockIdx.x;
    int tid = threadIdx.x;
    __shared__ float sv[MRG];
    __shared__ int   si[MRG];

    for (int i = tid; i < MRG; i += 256) {
        if (i < CANDM) { sv[i] = g_pv[b * CANDM + i]; si[i] = g_pi[b * CANDM + i]; }
        else           { sv[i] = finf();              si[i] = 0x7fffffff; }
    }
    __syncthreads();
    sort_sh<MRG>(sv, si, tid);

    if (tid < TOPK) {
        int ki = si[tid];
        if (ki < 0) ki = 0;
        if (ki >= NK) ki = NK - 1;   // fail-soft: never emit OOB index
        g_topk[b * TOPK + tid] = ki;
    }
}

// ---------------- K3: fp32 recompute (as reference) + weighting -------------
__global__ __launch_bounds__(128) void out_kernel(const float* __restrict__ Q,
                                                  const float* __restrict__ Kd,
                                                  const float* __restrict__ V,
                                                  float* __restrict__ out) {
    int b    = blockIdx.x;
    int lane = threadIdx.x & 31;
    int warp = threadIdx.x >> 5;
    __shared__ float sqd[TOPK];

    const float* qr = Q + (size_t)b * DIM;
    for (int j = warp; j < TOPK; j += 4) {
        int ki = g_topk[b * TOPK + j];
        const float* kr = Kd + (size_t)ki * DIM;
        float acc = 0.f;
#pragma unroll
        for (int m = 0; m < 4; m++) {
            float d = qr[lane + 32 * m] - kr[lane + 32 * m];
            float p = __fmul_rn(d, d);
            acc = __fadd_rn(acc, p);
        }
#pragma unroll
        for (int s = 16; s; s >>= 1) acc += __shfl_xor_sync(0xffffffffu, acc, s);
        if (lane == 0) sqd[j] = acc;
    }
    __syncthreads();

    if (threadIdx.x == 0) {
        float s1 = 0.f, s2 = 0.f;
        for (int j = 0; j < TOPK; j++) {
            float w = 1.f / (sqd[j] + DELTA);
            s1 += w;
            s2 += w * V[g_topk[b * TOPK + j]];
        }
        out[b] = s2 / s1;
    }
}

// ---------------- launch ----------------------------------------------------
extern "C" void kernel_launch(void* const* d_in, const int* in_sizes, int n_in,
                              void* d_out, int out_size) {
    const float* Q  = nullptr;   // 262144 elems
    const float* Kd = nullptr;   // 12800000 elems
    const float* V  = nullptr;   // 100000 elems
    for (int i = 0; i < n_in; i++) {
        if      (in_sizes[i] == BQ * DIM) Q  = (const float*)d_in[i];
        else if (in_sizes[i] == NK * DIM) Kd = (const float*)d_in[i];
        else if (in_sizes[i] == NK)       V  = (const float*)d_in[i];
    }
    float* out = (float*)d_out;
    if (!Q || !Kd || !V) return;

    norms_kernel<<<(NK + 7) / 8, 256>>>(Kd, NK, 0);
    norms_kernel<<<(BQ + 7) / 8, 256>>>(Q,  BQ, 1);

    dim3 grid((NK + BN - 1) / BN, BQ / BM);   // 1563 x 32
    score_gemm<<<grid, 256>>>(Q, Kd);

    dim3 tgrid(BQ, NPART);
    topk_part<<<tgrid, 256>>>();
    topk_merge<<<BQ, 256>>>();

    out_kernel<<<BQ, 128>>>(Q, Kd, V, out);
}

// round 9
// speedup vs baseline: 1.9717x; 1.9717x over previous
#include <cuda_runtime.h>
#include <cstdint>

// Problem constants (fixed shapes per reference setup_inputs)
#define BQ   2048      // queries
#define NK   100000    // capacity
#define DIM  128       // key size
#define TOPK 50
#define DELTA 1e-3f

// ---------------- scratch (static device globals; no runtime allocation) ----
__device__ float g_score[(size_t)BQ * NK];   // ~819 MB score matrix
__device__ float g_keynorm[NK];
__device__ float g_qnorm[BQ];
__device__ int   g_topk[BQ * TOPK];

static __device__ __forceinline__ float finf() { return __int_as_float(0x7f800000); }

// packed dual-fp32 FMA: each 32-bit lane rounds exactly like scalar FFMA (rn)
static __device__ __forceinline__ unsigned long long ffma2(unsigned long long a,
                                                           unsigned long long b,
                                                           unsigned long long c) {
    unsigned long long d;
    asm("fma.rn.f32x2 %0, %1, %2, %3;" : "=l"(d) : "l"(a), "l"(b), "l"(c));
    return d;
}
static __device__ __forceinline__ float lo32(unsigned long long v) {
    return __uint_as_float((unsigned int)(v & 0xffffffffull));
}
static __device__ __forceinline__ float hi32(unsigned long long v) {
    return __uint_as_float((unsigned int)(v >> 32));
}

// ---------------- K0: row squared norms, XLA row-reduce replica -------------
// (FROZEN — this exact rounding/grouping is what makes selection match)
__global__ void norms_kernel(const float* __restrict__ src, int rows, int which) {
    int warp = (blockIdx.x * blockDim.x + threadIdx.x) >> 5;
    int lane = threadIdx.x & 31;
    if (warp >= rows) return;
    const float* r = src + (size_t)warp * DIM;
    float acc = 0.f;
#pragma unroll
    for (int pass = 0; pass < 2; pass++) {
        int base = pass * 64 + 2 * lane;
        float v0 = r[base];
        float v1 = r[base + 1];
        acc = __fadd_rn(acc, __fmul_rn(v0, v0));
        acc = __fadd_rn(acc, __fmul_rn(v1, v1));
    }
#pragma unroll
    for (int s = 16; s; s >>= 1)
        acc = __fadd_rn(acc, __shfl_xor_sync(0xffffffffu, acc, s));
    if (lane == 0) {
        if (which == 0) g_keynorm[warp] = acc;
        else            g_qnorm[warp]   = acc;
    }
}

// ---------------- K1: FFMA2 GEMM -> scores (bit-identical to scalar) --------
// 64(m) x 128(n) tile, 4x8 per thread. A stored DUPLICATED in smem so both
// FFMA2 operands load directly via LDS.128 (no splat movs).
// Each output keeps its own fp32 lane: ascending-k fma.rn chain == scalar.
#define TM 64
#define TN 128
#define TKK 16
#define AST 132   // duplicated-A row stride (floats): 16B-aligned LDS, spread banks
#define BST 128

__global__ __launch_bounds__(256) void score_gemm(const float* __restrict__ Q,
                                                  const float* __restrict__ Kd) {
    __shared__ float As2[TKK][AST];   // [k][2*m+{0,1}] duplicated
    __shared__ float Bs[TKK][BST];    // [k][n]

    int n0 = blockIdx.x * TN;
    int b0 = blockIdx.y * TM;
    int tid = threadIdx.x;
    int tx = tid & 15;    // n group: 8 cols each
    int ty = tid >> 4;    // m group: 4 rows each

    unsigned long long acc[4][4];
#pragma unroll
    for (int i = 0; i < 4; i++)
#pragma unroll
        for (int j = 0; j < 4; j++) acc[i][j] = 0ull;

    int ar  = tid >> 2;          // A: row 0..63
    int ac4 = (tid & 3) * 4;     // A: k col {0,4,8,12}
    int br  = tid >> 1;          // B: row 0..127
    int bc8 = (tid & 1) * 8;     // B: k col {0,8}

    for (int k0 = 0; k0 < DIM; k0 += TKK) {
        float4 a = *(const float4*)(Q + (size_t)(b0 + ar) * DIM + k0 + ac4);
        int krow = n0 + br;
        float4 c0 = make_float4(0.f, 0.f, 0.f, 0.f);
        float4 c1 = make_float4(0.f, 0.f, 0.f, 0.f);
        if (krow < NK) {
            c0 = *(const float4*)(Kd + (size_t)krow * DIM + k0 + bc8);
            c1 = *(const float4*)(Kd + (size_t)krow * DIM + k0 + bc8 + 4);
        }
        __syncthreads();
        // duplicated A store: As2[k][2m] = As2[k][2m+1] = A[m][k]
        As2[ac4 + 0][2 * ar] = a.x; As2[ac4 + 0][2 * ar + 1] = a.x;
        As2[ac4 + 1][2 * ar] = a.y; As2[ac4 + 1][2 * ar + 1] = a.y;
        As2[ac4 + 2][2 * ar] = a.z; As2[ac4 + 2][2 * ar + 1] = a.z;
        As2[ac4 + 3][2 * ar] = a.w; As2[ac4 + 3][2 * ar + 1] = a.w;
        Bs[bc8 + 0][br] = c0.x; Bs[bc8 + 1][br] = c0.y;
        Bs[bc8 + 2][br] = c0.z; Bs[bc8 + 3][br] = c0.w;
        Bs[bc8 + 4][br] = c1.x; Bs[bc8 + 5][br] = c1.y;
        Bs[bc8 + 6][br] = c1.z; Bs[bc8 + 7][br] = c1.w;
        __syncthreads();

#pragma unroll
        for (int kk = 0; kk < TKK; kk++) {
            const ulonglong2* ap = reinterpret_cast<const ulonglong2*>(&As2[kk][ty * 8]);
            ulonglong2 a01 = ap[0];   // (A[m0],A[m0]) , (A[m1],A[m1])
            ulonglong2 a23 = ap[1];   // (A[m2],A[m2]) , (A[m3],A[m3])
            const ulonglong2* bp = reinterpret_cast<const ulonglong2*>(&Bs[kk][tx * 8]);
            ulonglong2 b01 = bp[0];   // (B[n0],B[n1]) , (B[n2],B[n3])
            ulonglong2 b23 = bp[1];   // (B[n4],B[n5]) , (B[n6],B[n7])

            acc[0][0] = ffma2(a01.x, b01.x, acc[0][0]);
            acc[0][1] = ffma2(a01.x, b01.y, acc[0][1]);
            acc[0][2] = ffma2(a01.x, b23.x, acc[0][2]);
            acc[0][3] = ffma2(a01.x, b23.y, acc[0][3]);
            acc[1][0] = ffma2(a01.y, b01.x, acc[1][0]);
            acc[1][1] = ffma2(a01.y, b01.y, acc[1][1]);
            acc[1][2] = ffma2(a01.y, b23.x, acc[1][2]);
            acc[1][3] = ffma2(a01.y, b23.y, acc[1][3]);
            acc[2][0] = ffma2(a23.x, b01.x, acc[2][0]);
            acc[2][1] = ffma2(a23.x, b01.y, acc[2][1]);
            acc[2][2] = ffma2(a23.x, b23.x, acc[2][2]);
            acc[2][3] = ffma2(a23.x, b23.y, acc[2][3]);
            acc[3][0] = ffma2(a23.y, b01.x, acc[3][0]);
            acc[3][1] = ffma2(a23.y, b01.y, acc[3][1]);
            acc[3][2] = ffma2(a23.y, b23.x, acc[3][2]);
            acc[3][3] = ffma2(a23.y, b23.y, acc[3][3]);
        }
    }

    // epilogue: (qn - 2*dot) + kn — frozen rounding sequence
    int nbase = n0 + tx * 8;
    bool ok0 = (nbase + 3) < NK;
    bool ok1 = (nbase + 7) < NK;
    float kn[8];
#pragma unroll
    for (int j = 0; j < 8; j++) kn[j] = (nbase + j < NK) ? g_keynorm[nbase + j] : 0.f;

#pragma unroll
    for (int i = 0; i < 4; i++) {
        int bb = b0 + ty * 4 + i;
        float qn = g_qnorm[bb];
        float c[8];
#pragma unroll
        for (int j = 0; j < 4; j++) { c[2 * j] = lo32(acc[i][j]); c[2 * j + 1] = hi32(acc[i][j]); }
        float r[8];
#pragma unroll
        for (int j = 0; j < 8; j++)
            r[j] = __fadd_rn(__fsub_rn(qn, 2.f * c[j]), kn[j]);
        float* dst = &g_score[(size_t)bb * NK + nbase];
        if (ok0) *(float4*)dst       = make_float4(r[0], r[1], r[2], r[3]);
        if (ok1) *(float4*)(dst + 4) = make_float4(r[4], r[5], r[6], r[7]);
    }
}

// ---------------- K2: exact top-50 via min-threshold two-pass ---------------
// Pass 1: per-thread min over strided segment; tau = 50th smallest of the 256
// minima (provable upper bound on the true 50th score: >=50 threads have
// min <= tau, each contributes >=1 value <= tau).
// Pass 2: collect all scores <= tau (expected ~60), sort by (value,index).
#define CAP 4096

__global__ __launch_bounds__(256) void topk_select() {
    int b   = blockIdx.x;
    int tid = threadIdx.x;
    const float4* row4 = (const float4*)(g_score + (size_t)b * NK);
    const int N4 = NK / 4;   // 25000

    __shared__ float smin[256];
    __shared__ float sv[CAP];
    __shared__ int   si[CAP];
    __shared__ int   s_cnt;

    // ---- pass 1: per-thread min ----
    float m = finf();
#pragma unroll 4
    for (int p = tid; p < N4; p += 256) {
        float4 v = row4[p];
        m = fminf(m, fminf(fminf(v.x, v.y), fminf(v.z, v.w)));
    }
    smin[tid] = m;
    __syncthreads();

    // bitonic sort 256 floats ascending (value only; ties harmless for tau)
    for (int k = 2; k <= 256; k <<= 1) {
        for (int j = k >> 1; j; j >>= 1) {
            int ixj = tid ^ j;
            if (ixj > tid) {
                float v1 = smin[tid], v2 = smin[ixj];
                bool up = ((tid & k) == 0);
                if ((v1 < v2) != up) { smin[tid] = v2; smin[ixj] = v1; }
            }
            __syncthreads();
        }
    }
    float tau = smin[TOPK - 1];
    if (tid == 0) s_cnt = 0;
    __syncthreads();

    // ---- pass 2: collect candidates <= tau ----
    for (int p = tid; p < N4; p += 256) {
        float4 v = row4[p];
        if (v.x <= tau) { int q = atomicAdd(&s_cnt, 1); if (q < CAP) { sv[q] = v.x; si[q] = 4 * p + 0; } }
        if (v.y <= tau) { int q = atomicAdd(&s_cnt, 1); if (q < CAP) { sv[q] = v.y; si[q] = 4 * p + 1; } }
        if (v.z <= tau) { int q = atomicAdd(&s_cnt, 1); if (q < CAP) { sv[q] = v.z; si[q] = 4 * p + 2; } }
        if (v.w <= tau) { int q = atomicAdd(&s_cnt, 1); if (q < CAP) { sv[q] = v.w; si[q] = 4 * p + 3; } }
    }
    __syncthreads();

    int cnt = s_cnt; if (cnt > CAP) cnt = CAP;
    int P = 64; while (P < cnt) P <<= 1;       // pow2 width >= cnt, >= 64
    for (int i = tid; i < P; i += 256)
        if (i >= cnt) { sv[i] = finf(); si[i] = 0x7fffffff; }
    __syncthreads();

    // bitonic sort P entries by (value, index) ascending — canonicalizes any
    // atomic push order into a deterministic result
    for (int k = 2; k <= P; k <<= 1) {
        for (int j = k >> 1; j; j >>= 1) {
            for (int i = tid; i < P; i += 256) {
                int ixj = i ^ j;
                if (ixj > i) {
                    float v1 = sv[i], v2 = sv[ixj];
                    int  i1 = si[i],  i2 = si[ixj];
                    bool up   = ((i & k) == 0);
                    bool less = (v1 < v2) || (v1 == v2 && i1 < i2);
                    if (less != up) {
                        sv[i] = v2; sv[ixj] = v1;
                        si[i] = i2; si[ixj] = i1;
                    }
                }
            }
            __syncthreads();
        }
    }

    if (tid < TOPK) {
        int ki = si[tid];
        if (ki < 0) ki = 0;
        if (ki >= NK) ki = NK - 1;   // fail-soft: never emit OOB index
        g_topk[b * TOPK + tid] = ki;
    }
}

// ---------------- K3: fp32 recompute (as reference) + weighting (FROZEN) ----
__global__ __launch_bounds__(128) void out_kernel(const float* __restrict__ Q,
                                                  const float* __restrict__ Kd,
                                                  const float* __restrict__ V,
                                                  float* __restrict__ out) {
    int b    = blockIdx.x;
    int lane = threadIdx.x & 31;
    int warp = threadIdx.x >> 5;
    __shared__ float sqd[TOPK];

    const float* qr = Q + (size_t)b * DIM;
    for (int j = warp; j < TOPK; j += 4) {
        int ki = g_topk[b * TOPK + j];
        const float* kr = Kd + (size_t)ki * DIM;
        float acc = 0.f;
#pragma unroll
        for (int m = 0; m < 4; m++) {
            float d = qr[lane + 32 * m] - kr[lane + 32 * m];
            float p = __fmul_rn(d, d);
            acc = __fadd_rn(acc, p);
        }
#pragma unroll
        for (int s = 16; s; s >>= 1) acc += __shfl_xor_sync(0xffffffffu, acc, s);
        if (lane == 0) sqd[j] = acc;
    }
    __syncthreads();

    if (threadIdx.x == 0) {
        float s1 = 0.f, s2 = 0.f;
        for (int j = 0; j < TOPK; j++) {
            float w = 1.f / (sqd[j] + DELTA);
            s1 += w;
            s2 += w * V[g_topk[b * TOPK + j]];
        }
        out[b] = s2 / s1;
    }
}

// ---------------- launch ----------------------------------------------------
extern "C" void kernel_launch(void* const* d_in, const int* in_sizes, int n_in,
                              void* d_out, int out_size) {
    const float* Q  = nullptr;   // 262144 elems
    const float* Kd = nullptr;   // 12800000 elems
    const float* V  = nullptr;   // 100000 elems
    for (int i = 0; i < n_in; i++) {
        if      (in_sizes[i] == BQ * DIM) Q  = (const float*)d_in[i];
        else if (in_sizes[i] == NK * DIM) Kd = (const float*)d_in[i];
        else if (in_sizes[i] == NK)       V  = (const float*)d_in[i];
    }
    float* out = (float*)d_out;
    if (!Q || !Kd || !V) return;

    norms_kernel<<<(NK + 7) / 8, 256>>>(Kd, NK, 0);
    norms_kernel<<<(BQ + 7) / 8, 256>>>(Q,  BQ, 1);

    dim3 grid((NK + TN - 1) / TN, BQ / TM);   // 782 x 32
    score_gemm<<<grid, 256>>>(Q, Kd);

    topk_select<<<BQ, 256>>>();

    out_kernel<<<BQ, 128>>>(Q, Kd, V, out);
}

// round 10
// speedup vs baseline: 2.9967x; 1.5198x over previous
#include <cuda_runtime.h>
#include <cstdint>

// Problem constants (fixed shapes per reference setup_inputs)
#define BQ   2048      // queries
#define NK   100000    // capacity
#define DIM  128       // key size
#define TOPK 50
#define DELTA 1e-3f

#define BM 64
#define BN 64
#define NB ((NK + BN - 1) / BN)     // 1563 key blocks

// ---------------- scratch (static device globals; no runtime allocation) ----
__device__ float g_score[(size_t)BQ * NK];   // ~819 MB score matrix
__device__ float g_bmin[(size_t)BQ * NB];    // per-(query, key-block) min, 12.8 MB
__device__ float g_keynorm[NK];
__device__ float g_qnorm[BQ];
__device__ int   g_topk[BQ * TOPK];

static __device__ __forceinline__ float finf() { return __int_as_float(0x7f800000); }

// ---------------- K0: row squared norms, XLA row-reduce replica -------------
// (FROZEN — this exact rounding/grouping is what makes selection match)
__global__ void norms_kernel(const float* __restrict__ src, int rows, int which) {
    int warp = (blockIdx.x * blockDim.x + threadIdx.x) >> 5;
    int lane = threadIdx.x & 31;
    if (warp >= rows) return;
    const float* r = src + (size_t)warp * DIM;
    float acc = 0.f;
#pragma unroll
    for (int pass = 0; pass < 2; pass++) {
        int base = pass * 64 + 2 * lane;
        float v0 = r[base];
        float v1 = r[base + 1];
        acc = __fadd_rn(acc, __fmul_rn(v0, v0));
        acc = __fadd_rn(acc, __fmul_rn(v1, v1));
    }
#pragma unroll
    for (int s = 16; s; s >>= 1)
        acc = __fadd_rn(acc, __shfl_xor_sync(0xffffffffu, acc, s));
    if (lane == 0) {
        if (which == 0) g_keynorm[warp] = acc;
        else            g_qnorm[warp]   = acc;
    }
}

// ---------------- K1: fp32 tiled GEMM -> scores + block minima --------------
// (numerics FROZEN: ascending-k single-accumulator FMA dot; epilogue
//  (qn - 2*acc) + kn with __fsub_rn/__fadd_rn — bit-identical to round 6)
#define BKK 16
#define PADL 72

__global__ __launch_bounds__(256) void score_gemm(const float* __restrict__ Q,
                                                  const float* __restrict__ Kd) {
    __shared__ float As[BKK][PADL];
    __shared__ float Bs[BKK][PADL];

    int n0 = blockIdx.x * BN;
    int b0 = blockIdx.y * BM;
    int tid = threadIdx.x;
    int tx = tid & 15;
    int ty = tid >> 4;

    float acc[4][4];
#pragma unroll
    for (int i = 0; i < 4; i++)
#pragma unroll
        for (int j = 0; j < 4; j++) acc[i][j] = 0.f;

    int lr = tid >> 2;
    int lc = (tid & 3) * 4;

    for (int k0 = 0; k0 < DIM; k0 += BKK) {
        float4 a = *(const float4*)(Q + (size_t)(b0 + lr) * DIM + k0 + lc);
        int nrow = n0 + lr;
        float4 bv = make_float4(0.f, 0.f, 0.f, 0.f);
        if (nrow < NK)
            bv = *(const float4*)(Kd + (size_t)nrow * DIM + k0 + lc);

        __syncthreads();
        As[lc + 0][lr] = a.x;  As[lc + 1][lr] = a.y;
        As[lc + 2][lr] = a.z;  As[lc + 3][lr] = a.w;
        Bs[lc + 0][lr] = bv.x; Bs[lc + 1][lr] = bv.y;
        Bs[lc + 2][lr] = bv.z; Bs[lc + 3][lr] = bv.w;
        __syncthreads();

#pragma unroll
        for (int kk = 0; kk < BKK; kk++) {
            float4 av = *(const float4*)&As[kk][ty * 4];
            float4 bw = *(const float4*)&Bs[kk][tx * 4];
            float a_[4] = {av.x, av.y, av.z, av.w};
            float b_[4] = {bw.x, bw.y, bw.z, bw.w};
#pragma unroll
            for (int i = 0; i < 4; i++)
#pragma unroll
                for (int j = 0; j < 4; j++)
                    acc[i][j] = fmaf(a_[i], b_[j], acc[i][j]);   // ascending k
        }
    }

    int nbase = n0 + tx * 4;
    bool wr = (nbase + 3) < NK;   // all-valid per r6 geometry (valid cols always pass)
    float kn[4];
#pragma unroll
    for (int j = 0; j < 4; j++) kn[j] = (nbase + j < NK) ? g_keynorm[nbase + j] : 0.f;

#pragma unroll
    for (int i = 0; i < 4; i++) {
        int bb = b0 + ty * 4 + i;
        float qn = g_qnorm[bb];
        float r[4];
#pragma unroll
        for (int j = 0; j < 4; j++)
            r[j] = __fadd_rn(__fsub_rn(qn, 2.f * acc[i][j]), kn[j]);
        if (wr)
            *(float4*)&g_score[(size_t)bb * NK + nbase] =
                make_float4(r[0], r[1], r[2], r[3]);

        // ---- block-min epilogue (new; does not touch score numerics) ----
        float rmin = finf();
#pragma unroll
        for (int j = 0; j < 4; j++)
            if (nbase + j < NK) rmin = fminf(rmin, r[j]);
        // reduce across the 16 tx-lanes of this row (same 16-lane half-warp)
#pragma unroll
        for (int s = 1; s < 16; s <<= 1)
            rmin = fminf(rmin, __shfl_xor_sync(0xffffffffu, rmin, s));
        if (tx == 0)
            g_bmin[(size_t)bb * NB + blockIdx.x] = rmin;
    }
}

// ---------------- K2: exact top-50 via block-min filtered two-pass ----------
// tau = 50th smallest of 256 per-thread minima over block-mins (upper bound
// on the true 50th score). Pass 2 scans ONLY blocks with min <= tau and
// collects scores <= tau; bitonic sort by (value,index) canonicalizes.
#define CAP 2048

__global__ __launch_bounds__(256) void topk_select() {
    int b   = blockIdx.x;
    int tid = threadIdx.x;
    const float* bmin = g_bmin + (size_t)b * NB;
    const float* row  = g_score + (size_t)b * NK;

    __shared__ float smin[256];
    __shared__ float sv[CAP];
    __shared__ int   si[CAP];
    __shared__ int   s_cnt;

    // ---- pass 1: tau from block minima (12.8 MB total across grid) ----
    float m = finf();
    for (int p = tid; p < NB; p += 256) m = fminf(m, bmin[p]);
    smin[tid] = m;
    __syncthreads();

    // bitonic sort 256 floats ascending (value only; ties harmless for tau)
    for (int k = 2; k <= 256; k <<= 1) {
        for (int j = k >> 1; j; j >>= 1) {
            int ixj = tid ^ j;
            if (ixj > tid) {
                float v1 = smin[tid], v2 = smin[ixj];
                bool up = ((tid & k) == 0);
                if ((v1 < v2) != up) { smin[tid] = v2; smin[ixj] = v1; }
            }
            __syncthreads();
        }
    }
    float tau = smin[TOPK - 1];
    if (tid == 0) s_cnt = 0;
    __syncthreads();

    // ---- pass 2: scan only blocks whose min <= tau ----
    for (int p = tid; p < NB; p += 256) {
        if (bmin[p] <= tau) {
            int base = p * BN;
            int lim  = min(BN, NK - base);
            const float4* blk = (const float4*)(row + base);
#pragma unroll 4
            for (int e4 = 0; e4 < BN / 4; e4++) {
                if (e4 * 4 >= lim) break;
                float4 v = blk[e4];
                float vv[4] = {v.x, v.y, v.z, v.w};
#pragma unroll
                for (int e = 0; e < 4; e++) {
                    int n = base + e4 * 4 + e;
                    if (n < NK && vv[e] <= tau) {
                        int q = atomicAdd(&s_cnt, 1);
                        if (q < CAP) { sv[q] = vv[e]; si[q] = n; }
                    }
                }
            }
        }
    }
    __syncthreads();

    int cnt = s_cnt; if (cnt > CAP) cnt = CAP;
    int P = 64; while (P < cnt) P <<= 1;       // pow2 width >= cnt, >= 64
    for (int i = tid; i < P; i += 256)
        if (i >= cnt) { sv[i] = finf(); si[i] = 0x7fffffff; }
    __syncthreads();

    // bitonic sort by (value, index) ascending — deterministic result
    for (int k = 2; k <= P; k <<= 1) {
        for (int j = k >> 1; j; j >>= 1) {
            for (int i = tid; i < P; i += 256) {
                int ixj = i ^ j;
                if (ixj > i) {
                    float v1 = sv[i], v2 = sv[ixj];
                    int  i1 = si[i],  i2 = si[ixj];
                    bool up   = ((i & k) == 0);
                    bool less = (v1 < v2) || (v1 == v2 && i1 < i2);
                    if (less != up) {
                        sv[i] = v2; sv[ixj] = v1;
                        si[i] = i2; si[ixj] = i1;
                    }
                }
            }
            __syncthreads();
        }
    }

    if (tid < TOPK) {
        int ki = si[tid];
        if (ki < 0) ki = 0;
        if (ki >= NK) ki = NK - 1;   // fail-soft: never emit OOB index
        g_topk[b * TOPK + tid] = ki;
    }
}

// ---------------- K3: fp32 recompute (as reference) + weighting (FROZEN) ----
__global__ __launch_bounds__(128) void out_kernel(const float* __restrict__ Q,
                                                  const float* __restrict__ Kd,
                                                  const float* __restrict__ V,
                                                  float* __restrict__ out) {
    int b    = blockIdx.x;
    int lane = threadIdx.x & 31;
    int warp = threadIdx.x >> 5;
    __shared__ float sqd[TOPK];

    const float* qr = Q + (size_t)b * DIM;
    for (int j = warp; j < TOPK; j += 4) {
        int ki = g_topk[b * TOPK + j];
        const float* kr = Kd + (size_t)ki * DIM;
        float acc = 0.f;
#pragma unroll
        for (int m = 0; m < 4; m++) {
            float d = qr[lane + 32 * m] - kr[lane + 32 * m];
            float p = __fmul_rn(d, d);
            acc = __fadd_rn(acc, p);
        }
#pragma unroll
        for (int s = 16; s; s >>= 1) acc += __shfl_xor_sync(0xffffffffu, acc, s);
        if (lane == 0) sqd[j] = acc;
    }
    __syncthreads();

    if (threadIdx.x == 0) {
        float s1 = 0.f, s2 = 0.f;
        for (int j = 0; j < TOPK; j++) {
            float w = 1.f / (sqd[j] + DELTA);
            s1 += w;
            s2 += w * V[g_topk[b * TOPK + j]];
        }
        out[b] = s2 / s1;
    }
}

// ---------------- launch ----------------------------------------------------
extern "C" void kernel_launch(void* const* d_in, const int* in_sizes, int n_in,
                              void* d_out, int out_size) {
    const float* Q  = nullptr;   // 262144 elems
    const float* Kd = nullptr;   // 12800000 elems
    const float* V  = nullptr;   // 100000 elems
    for (int i = 0; i < n_in; i++) {
        if      (in_sizes[i] == BQ * DIM) Q  = (const float*)d_in[i];
        else if (in_sizes[i] == NK * DIM) Kd = (const float*)d_in[i];
        else if (in_sizes[i] == NK)       V  = (const float*)d_in[i];
    }
    float* out = (float*)d_out;
    if (!Q || !Kd || !V) return;

    norms_kernel<<<(NK + 7) / 8, 256>>>(Kd, NK, 0);
    norms_kernel<<<(BQ + 7) / 8, 256>>>(Q,  BQ, 1);

    dim3 grid((NK + BN - 1) / BN, BQ / BM);   // 1563 x 32
    score_gemm<<<grid, 256>>>(Q, Kd);

    topk_select<<<BQ, 256>>>();

    out_kernel<<<BQ, 128>>>(Q, Kd, V, out);
}

// round 11
// speedup vs baseline: 8.6634x; 2.8910x over previous
#include <cuda_runtime.h>
#include <cuda_fp16.h>
#include <cuda_bf16.h>
#include <cstdint>

// Problem constants (fixed shapes per reference setup_inputs)
#define BQ   2048      // queries
#define NK   100000    // capacity
#define DIM  128       // key size
#define TOPK 50
#define DELTA 1e-3f

#define NKP   100096                 // NK padded to multiple of 128 (782*128)
#define NBLK  (NKP / 64)             // 1564 64-key blocks
#define MARG  0.75f                  // screening error margin (>= bf16+fp16 err)
#define CAP   4096

// ---------------- scratch (static device globals; no runtime allocation) ----
__device__ __half         g_sh[(size_t)BQ * NKP];      // fp16 approx scores, 410 MB
__device__ __nv_bfloat16  g_Qb[(size_t)BQ * DIM];
__device__ __nv_bfloat16  g_Kb[(size_t)NKP * DIM];
__device__ float          g_bmin[(size_t)BQ * NBLK];   // per-(q, 64-block) min of stored fp16
__device__ float          g_keynorm[NK];
__device__ float          g_qnorm[BQ];
__device__ int            g_topk[BQ * TOPK];

static __device__ __forceinline__ float finf() { return __int_as_float(0x7f800000); }

// ---------------- K0: row squared norms, XLA row-reduce replica (FROZEN) ----
__global__ void norms_kernel(const float* __restrict__ src, int rows, int which) {
    int warp = (blockIdx.x * blockDim.x + threadIdx.x) >> 5;
    int lane = threadIdx.x & 31;
    if (warp >= rows) return;
    const float* r = src + (size_t)warp * DIM;
    float acc = 0.f;
#pragma unroll
    for (int pass = 0; pass < 2; pass++) {
        int base = pass * 64 + 2 * lane;
        float v0 = r[base];
        float v1 = r[base + 1];
        acc = __fadd_rn(acc, __fmul_rn(v0, v0));
        acc = __fadd_rn(acc, __fmul_rn(v1, v1));
    }
#pragma unroll
    for (int s = 16; s; s >>= 1)
        acc = __fadd_rn(acc, __shfl_xor_sync(0xffffffffu, acc, s));
    if (lane == 0) {
        if (which == 0) g_keynorm[warp] = acc;
        else            g_qnorm[warp]   = acc;
    }
}

// ---------------- K0b: fp32 -> bf16 conversion (zero-pad beyond n_src) ------
__global__ void cvt_bf16(const float* __restrict__ src, __nv_bfloat16* __restrict__ dst,
                         int n_src, int n_dst) {
    int i = blockIdx.x * blockDim.x + threadIdx.x;
    if (i < n_dst) dst[i] = __float2bfloat16(i < n_src ? src[i] : 0.f);
}

// ---------------- K1: bf16 tensor-core screening GEMM -----------------------
// CTA: 64 queries x 128 keys, 8 warps (warpM in 0..3 -> m16, warpN in 0..1 -> n64).
// s~ = qn - 2*dot_bf16 + kn (exact fp32 norms), stored fp16 + 64-block mins.
#define SAS 136   // smem row stride in halves (272B: 16B-aligned, conflict-free)

static __device__ __forceinline__ void mma16816(float acc[4],
                                                uint32_t a0, uint32_t a1, uint32_t a2, uint32_t a3,
                                                uint32_t b0, uint32_t b1) {
    asm volatile(
        "mma.sync.aligned.m16n8k16.row.col.f32.bf16.bf16.f32 "
        "{%0,%1,%2,%3}, {%4,%5,%6,%7}, {%8,%9}, {%0,%1,%2,%3};\n"
        : "+f"(acc[0]), "+f"(acc[1]), "+f"(acc[2]), "+f"(acc[3])
        : "r"(a0), "r"(a1), "r"(a2), "r"(a3), "r"(b0), "r"(b1));
}

__global__ __launch_bounds__(256) void screen_gemm() {
    extern __shared__ __align__(16) unsigned char sm_raw[];
    __half* As = (__half*)sm_raw;            // 64  x SAS
    __half* Bs = As + 64 * SAS;              // 128 x SAS

    int tid  = threadIdx.x;
    int w    = tid >> 5;
    int lane = tid & 31;
    int warpM = w & 3;
    int warpN = w >> 2;
    int n0  = blockIdx.x * 128;
    int b0q = blockIdx.y * 64;

    // stage A (64x128 bf16) and B (128x128 bf16) with padded stride
    for (int i = tid; i < 64 * 16; i += 256) {
        int row = i >> 4, ch = i & 15;
        uint4 v = *(const uint4*)(g_Qb + (size_t)(b0q + row) * DIM + ch * 8);
        *(uint4*)((char*)As + row * (SAS * 2) + ch * 16) = v;
    }
    for (int i = tid; i < 128 * 16; i += 256) {
        int row = i >> 4, ch = i & 15;
        uint4 v = *(const uint4*)(g_Kb + (size_t)(n0 + row) * DIM + ch * 8);
        *(uint4*)((char*)Bs + row * (SAS * 2) + ch * 16) = v;
    }
    __syncthreads();

    float acc[8][4];
#pragma unroll
    for (int t = 0; t < 8; t++)
#pragma unroll
        for (int j = 0; j < 4; j++) acc[t][j] = 0.f;

    int ar = warpM * 16 + (lane >> 2);       // A row (m), rows ar and ar+8
    int ac = (lane & 3) * 2;                 // k within 16-step
    int bn = warpN * 64 + (lane >> 2);       // B row (n) base; tiles add t*8

#pragma unroll
    for (int ks = 0; ks < 8; ks++) {
        int k0 = ks * 16;
        uint32_t a0 = *(const uint32_t*)&As[ar * SAS + k0 + ac];
        uint32_t a1 = *(const uint32_t*)&As[(ar + 8) * SAS + k0 + ac];
        uint32_t a2 = *(const uint32_t*)&As[ar * SAS + k0 + ac + 8];
        uint32_t a3 = *(const uint32_t*)&As[(ar + 8) * SAS + k0 + ac + 8];
#pragma unroll
        for (int t = 0; t < 8; t++) {
            uint32_t b0v = *(const uint32_t*)&Bs[(bn + t * 8) * SAS + k0 + ac];
            uint32_t b1v = *(const uint32_t*)&Bs[(bn + t * 8) * SAS + k0 + ac + 8];
            mma16816(acc[t], a0, a1, a2, a3, b0v, b1v);
        }
    }

    // epilogue: s~ = qn - 2*dot + kn ; store fp16, track per-row block-min
    int gq0 = b0q + warpM * 16 + (lane >> 2);
    int gq1 = gq0 + 8;
    float qn0 = g_qnorm[gq0];
    float qn1 = g_qnorm[gq1];
    float mn0 = finf(), mn1 = finf();

#pragma unroll
    for (int t = 0; t < 8; t++) {
        int gn = n0 + warpN * 64 + t * 8 + (lane & 3) * 2;
        bool v0 = gn < NK, v1 = (gn + 1) < NK;
        float kn0 = v0 ? g_keynorm[gn] : 0.f;
        float kn1 = v1 ? g_keynorm[gn + 1] : 0.f;
        float s00 = v0 ? (qn0 - 2.f * acc[t][0] + kn0) : finf();
        float s01 = v1 ? (qn0 - 2.f * acc[t][1] + kn1) : finf();
        float s10 = v0 ? (qn1 - 2.f * acc[t][2] + kn0) : finf();
        float s11 = v1 ? (qn1 - 2.f * acc[t][3] + kn1) : finf();
        __half h00 = __float2half(s00), h01 = __float2half(s01);
        __half h10 = __float2half(s10), h11 = __float2half(s11);
        __half2 p0; p0.x = h00; p0.y = h01;
        __half2 p1; p1.x = h10; p1.y = h11;
        *(__half2*)(g_sh + (size_t)gq0 * NKP + gn) = p0;
        *(__half2*)(g_sh + (size_t)gq1 * NKP + gn) = p1;
        mn0 = fminf(mn0, fminf(__half2float(h00), __half2float(h01)));
        mn1 = fminf(mn1, fminf(__half2float(h10), __half2float(h11)));
    }
    // reduce over the 4 lanes sharing these rows (lane bits 0-1)
#pragma unroll
    for (int s = 1; s < 4; s <<= 1) {
        mn0 = fminf(mn0, __shfl_xor_sync(0xffffffffu, mn0, s));
        mn1 = fminf(mn1, __shfl_xor_sync(0xffffffffu, mn1, s));
    }
    if ((lane & 3) == 0) {
        int blk = blockIdx.x * 2 + warpN;
        g_bmin[(size_t)gq0 * NBLK + blk] = mn0;
        g_bmin[(size_t)gq1 * NBLK + blk] = mn1;
    }
}

// ---------------- K2: select via screen + EXACT frozen-chain rescore --------
__global__ __launch_bounds__(256) void topk_sel(const float* __restrict__ Q,
                                                const float* __restrict__ Kd) {
    int b    = blockIdx.x;
    int tid  = threadIdx.x;
    int w    = tid >> 5;
    int lane = tid & 31;

    __shared__ float smin[256];
    __shared__ float sv[CAP];
    __shared__ int   si[CAP];
    __shared__ float qrow[DIM];
    __shared__ float kbuf[8][DIM];
    __shared__ int   s_cnt;

    const float* bm = g_bmin + (size_t)b * NBLK;

    // ---- pass 1: tau from block minima ----
    float m = finf();
    for (int p = tid; p < NBLK; p += 256) m = fminf(m, bm[p]);
    smin[tid] = m;
    if (tid == 0) s_cnt = 0;
    for (int k = tid; k < DIM; k += 256) qrow[k] = Q[(size_t)b * DIM + k];
    __syncthreads();

    for (int k = 2; k <= 256; k <<= 1) {
        for (int j = k >> 1; j; j >>= 1) {
            int ixj = tid ^ j;
            if (ixj > tid) {
                float v1 = smin[tid], v2 = smin[ixj];
                bool up = ((tid & k) == 0);
                if ((v1 < v2) != up) { smin[tid] = v2; smin[ixj] = v1; }
            }
            __syncthreads();
        }
    }
    float T2 = smin[TOPK - 1] + 2.f * MARG;   // collect threshold (superset bound)
    __syncthreads();

    // ---- pass 2: candidates from fp16 screen matrix (warp per block) ----
    const __half* srow = g_sh + (size_t)b * NKP;
    for (int p = w; p < NBLK; p += 8) {
        if (bm[p] <= T2) {
            int nb = p * 64 + lane * 2;
            __half2 h2 = *(const __half2*)(srow + nb);
            float f0 = __half2float(h2.x);
            float f1 = __half2float(h2.y);
            if (nb < NK && f0 <= T2) {
                int q = atomicAdd(&s_cnt, 1);
                if (q < CAP) si[q] = nb;
            }
            if (nb + 1 < NK && f1 <= T2) {
                int q = atomicAdd(&s_cnt, 1);
                if (q < CAP) si[q] = nb + 1;
            }
        }
    }
    __syncthreads();
    int cnt = s_cnt; if (cnt > CAP) cnt = CAP;

    // ---- exact rescore with the FROZEN chain (warp per candidate) ----
    float qn = g_qnorm[b];
    for (int c = w; c < cnt; c += 8) {
        int n = si[c];
        float4 kv = *(const float4*)(Kd + (size_t)n * DIM + lane * 4);
        *(float4*)&kbuf[w][lane * 4] = kv;
        __syncwarp();
        if (lane == 0) {
            float acc = 0.f;
#pragma unroll
            for (int k = 0; k < DIM; k++)
                acc = fmaf(qrow[k], kbuf[w][k], acc);   // ascending k, FMA — frozen
            sv[c] = __fadd_rn(__fsub_rn(qn, 2.f * acc), g_keynorm[n]);
        }
        __syncwarp();
    }
    __syncthreads();

    int P = 64; while (P < cnt) P <<= 1;
    for (int i = tid; i < P; i += 256)
        if (i >= cnt) { sv[i] = finf(); si[i] = 0x7fffffff; }
    __syncthreads();

    // bitonic sort by (value, index) ascending — canonical, deterministic
    for (int k = 2; k <= P; k <<= 1) {
        for (int j = k >> 1; j; j >>= 1) {
            for (int i = tid; i < P; i += 256) {
                int ixj = i ^ j;
                if (ixj > i) {
                    float v1 = sv[i], v2 = sv[ixj];
                    int  i1 = si[i],  i2 = si[ixj];
                    bool up   = ((i & k) == 0);
                    bool less = (v1 < v2) || (v1 == v2 && i1 < i2);
                    if (less != up) {
                        sv[i] = v2; sv[ixj] = v1;
                        si[i] = i2; si[ixj] = i1;
                    }
                }
            }
            __syncthreads();
        }
    }

    if (tid < TOPK) {
        int ki = si[tid];
        if (ki < 0) ki = 0;
        if (ki >= NK) ki = NK - 1;   // fail-soft: never emit OOB index
        g_topk[b * TOPK + tid] = ki;
    }
}

// ---------------- K3: fp32 recompute (as reference) + weighting (FROZEN) ----
__global__ __launch_bounds__(128) void out_kernel(const float* __restrict__ Q,
                                                  const float* __restrict__ Kd,
                                                  const float* __restrict__ V,
                                                  float* __restrict__ out) {
    int b    = blockIdx.x;
    int lane = threadIdx.x & 31;
    int warp = threadIdx.x >> 5;
    __shared__ float sqd[TOPK];

    const float* qr = Q + (size_t)b * DIM;
    for (int j = warp; j < TOPK; j += 4) {
        int ki = g_topk[b * TOPK + j];
        const float* kr = Kd + (size_t)ki * DIM;
        float acc = 0.f;
#pragma unroll
        for (int m = 0; m < 4; m++) {
            float d = qr[lane + 32 * m] - kr[lane + 32 * m];
            float p = __fmul_rn(d, d);
            acc = __fadd_rn(acc, p);
        }
#pragma unroll
        for (int s = 16; s; s >>= 1) acc += __shfl_xor_sync(0xffffffffu, acc, s);
        if (lane == 0) sqd[j] = acc;
    }
    __syncthreads();

    if (threadIdx.x == 0) {
        float s1 = 0.f, s2 = 0.f;
        for (int j = 0; j < TOPK; j++) {
            float w = 1.f / (sqd[j] + DELTA);
            s1 += w;
            s2 += w * V[g_topk[b * TOPK + j]];
        }
        out[b] = s2 / s1;
    }
}

// ---------------- launch ----------------------------------------------------
extern "C" void kernel_launch(void* const* d_in, const int* in_sizes, int n_in,
                              void* d_out, int out_size) {
    const float* Q  = nullptr;   // 262144 elems
    const float* Kd = nullptr;   // 12800000 elems
    const float* V  = nullptr;   // 100000 elems
    for (int i = 0; i < n_in; i++) {
        if      (in_sizes[i] == BQ * DIM) Q  = (const float*)d_in[i];
        else if (in_sizes[i] == NK * DIM) Kd = (const float*)d_in[i];
        else if (in_sizes[i] == NK)       V  = (const float*)d_in[i];
    }
    float* out = (float*)d_out;
    if (!Q || !Kd || !V) return;

    norms_kernel<<<(NK + 7) / 8, 256>>>(Kd, NK, 0);
    norms_kernel<<<(BQ + 7) / 8, 256>>>(Q,  BQ, 1);

    // bf16 copies (zero-padded keys)
    {
        __nv_bfloat16* qb = nullptr; cudaGetSymbolAddress((void**)&qb, g_Qb);
        __nv_bfloat16* kb = nullptr; cudaGetSymbolAddress((void**)&kb, g_Kb);
        int nq = BQ * DIM;
        int nk = NKP * DIM;
        cvt_bf16<<<(nq + 255) / 256, 256>>>(Q,  qb, nq,        nq);
        cvt_bf16<<<(nk + 255) / 256, 256>>>(Kd, kb, NK * DIM,  nk);
    }

    // screening GEMM (dynamic smem 52224B)
    static int smem_set = 0;
    int smem_bytes = (64 + 128) * SAS * 2;
    if (!smem_set) {
        cudaFuncSetAttribute(screen_gemm, cudaFuncAttributeMaxDynamicSharedMemorySize,
                             smem_bytes);
        smem_set = 1;
    }
    dim3 sgrid(NKP / 128, BQ / 64);   // 782 x 32
    screen_gemm<<<sgrid, 256, smem_bytes>>>();

    topk_sel<<<BQ, 256>>>(Q, Kd);

    out_kernel<<<BQ, 128>>>(Q, Kd, V, out);
}

// round 14
// speedup vs baseline: 9.0568x; 1.0454x over previous
#include <cuda_runtime.h>
#include <cuda_fp16.h>
#include <cuda_bf16.h>
#include <cstdint>

// Problem constants (fixed shapes per reference setup_inputs)
#define BQ   2048      // queries
#define NK   100000    // capacity
#define DIM  128       // key size
#define TOPK 50
#define DELTA 1e-3f

#define NKP   100096                 // NK padded to multiple of 128 (782*128)
#define NBLK  (NKP / 64)             // 1564 64-key blocks
#define MARG  0.75f                  // screening error margin (>= bf16+fp16 err)
#define CAP   4096

// ---------------- scratch (static device globals; no runtime allocation) ----
__device__ __half         g_sh[(size_t)BQ * NKP];      // fp16 approx scores, 410 MB
__device__ __nv_bfloat16  g_Qb[(size_t)BQ * DIM];
__device__ __nv_bfloat16  g_Kb[(size_t)NKP * DIM];
__device__ float          g_bmin[(size_t)BQ * NBLK];   // per-(q, 64-block) min of stored fp16
__device__ float          g_keynorm[NK];
__device__ float          g_qnorm[BQ];
__device__ int            g_topk[BQ * TOPK];

static __device__ __forceinline__ float finf() { return __int_as_float(0x7f800000); }

static __device__ __forceinline__ uint32_t smem_u32(const void* p) {
    uint32_t a;
    asm("{ .reg .u64 t; cvta.to.shared.u64 t, %1; cvt.u32.u64 %0, t; }" : "=r"(a) : "l"(p));
    return a;
}

// ---------------- K0: row squared norms, XLA row-reduce replica (FROZEN) ----
__global__ void norms_kernel(const float* __restrict__ src, int rows, int which) {
    int warp = (blockIdx.x * blockDim.x + threadIdx.x) >> 5;
    int lane = threadIdx.x & 31;
    if (warp >= rows) return;
    const float* r = src + (size_t)warp * DIM;
    float acc = 0.f;
#pragma unroll
    for (int pass = 0; pass < 2; pass++) {
        int base = pass * 64 + 2 * lane;
        float v0 = r[base];
        float v1 = r[base + 1];
        acc = __fadd_rn(acc, __fmul_rn(v0, v0));
        acc = __fadd_rn(acc, __fmul_rn(v1, v1));
    }
#pragma unroll
    for (int s = 16; s; s >>= 1)
        acc = __fadd_rn(acc, __shfl_xor_sync(0xffffffffu, acc, s));
    if (lane == 0) {
        if (which == 0) g_keynorm[warp] = acc;
        else            g_qnorm[warp]   = acc;
    }
}

// ---------------- K0b: fp32 -> bf16 conversion, 4 elems/thread --------------
__global__ void cvt_bf16(const float* __restrict__ src, __nv_bfloat16* __restrict__ dst,
                         int n_src, int n_dst) {
    int i4 = (blockIdx.x * blockDim.x + threadIdx.x) * 4;
    if (i4 >= n_dst) return;
    float4 v = make_float4(0.f, 0.f, 0.f, 0.f);
    if (i4 + 3 < n_src) v = *(const float4*)(src + i4);
    else {
        if (i4 + 0 < n_src) v.x = src[i4 + 0];
        if (i4 + 1 < n_src) v.y = src[i4 + 1];
        if (i4 + 2 < n_src) v.z = src[i4 + 2];
        if (i4 + 3 < n_src) v.w = src[i4 + 3];
    }
    __nv_bfloat162 p0 = __floats2bfloat162_rn(v.x, v.y);
    __nv_bfloat162 p1 = __floats2bfloat162_rn(v.z, v.w);
    *(uint2*)(dst + i4) = make_uint2(*(uint32_t*)&p0, *(uint32_t*)&p1);
}

// ---------------- K1: bf16 mma.sync screening GEMM, ldmatrix fragments ------
// CTA: 128 q x 128 k, 8 warps. Warp tile: 32m x 64n (warpM 0..3, warpN 0..1).
// s~ = qn - 2*dot_bf16 + kn (exact fp32 norms), fp16 store + 64-block mins.
#define SAS 136   // smem row stride in halves (272B -> ldmatrix conflict-free)

static __device__ __forceinline__ void mma16816(float acc[4],
                                                uint32_t a0, uint32_t a1, uint32_t a2, uint32_t a3,
                                                uint32_t b0, uint32_t b1) {
    asm volatile(
        "mma.sync.aligned.m16n8k16.row.col.f32.bf16.bf16.f32 "
        "{%0,%1,%2,%3}, {%4,%5,%6,%7}, {%8,%9}, {%0,%1,%2,%3};\n"
        : "+f"(acc[0]), "+f"(acc[1]), "+f"(acc[2]), "+f"(acc[3])
        : "r"(a0), "r"(a1), "r"(a2), "r"(a3), "r"(b0), "r"(b1));
}
static __device__ __forceinline__ void ldsm_x4(uint32_t& r0, uint32_t& r1,
                                               uint32_t& r2, uint32_t& r3, uint32_t addr) {
    asm volatile("ldmatrix.sync.aligned.m8n8.x4.shared.b16 {%0,%1,%2,%3}, [%4];"
                 : "=r"(r0), "=r"(r1), "=r"(r2), "=r"(r3) : "r"(addr));
}

#define SMEM_TOT (2 * 128 * SAS * 2)   // A + B, 69632 B

__global__ __launch_bounds__(256) void screen_gemm() {
    extern __shared__ __align__(16) unsigned char smraw[];
    uint32_t smbA = smem_u32(smraw);
    uint32_t smbB = smbA + 128 * SAS * 2;

    int tid  = threadIdx.x;
    int wid  = tid >> 5;
    int lane = tid & 31;
    int warpM = wid & 3;   // 32 q rows each
    int warpN = wid >> 2;  // 64 k cols each
    int n0   = blockIdx.x * 128;
    int b0q  = blockIdx.y * 128;

    // stage A (128 q rows) and B (128 key rows), row-major, padded stride
    for (int i = tid; i < 128 * 16; i += 256) {
        int row = i >> 4, ch = i & 15;   // ch = 16B chunk (8 bf16)
        uint4 va = *(const uint4*)(g_Qb + (size_t)(b0q + row) * DIM + ch * 8);
        *(uint4*)(smraw + (row * SAS + ch * 8) * 2) = va;
        uint4 vb = *(const uint4*)(g_Kb + (size_t)(n0 + row) * DIM + ch * 8);
        *(uint4*)(smraw + 128 * SAS * 2 + (row * SAS + ch * 8) * 2) = vb;
    }
    __syncthreads();

    float acc[2][8][4];
#pragma unroll
    for (int mi = 0; mi < 2; mi++)
#pragma unroll
        for (int ni = 0; ni < 8; ni++)
#pragma unroll
            for (int j = 0; j < 4; j++) acc[mi][ni][j] = 0.f;

    // ldmatrix lane addressing: matrix j = lane>>3, row-in-matrix = lane&7
    int lj  = lane >> 3;
    int ljr = lane & 7;

#pragma unroll
    for (int ks = 0; ks < 8; ks++) {
        int k0 = ks * 16;
        // A fragments: mi selects 16-row sub-tile
        uint32_t a[2][4];
#pragma unroll
        for (int mi = 0; mi < 2; mi++) {
            int arow = warpM * 32 + mi * 16 + (lj & 1) * 8 + ljr;
            uint32_t ad = smbA + (uint32_t)((arow * SAS + k0 + (lj >> 1) * 8) * 2);
            ldsm_x4(a[mi][0], a[mi][1], a[mi][2], a[mi][3], ad);
        }
        // B fragments: nj covers 16 keys (two n8 blocks)
        uint32_t bfr[4][4];
#pragma unroll
        for (int nj = 0; nj < 4; nj++) {
            int brow = warpN * 64 + nj * 16 + (lj >> 1) * 8 + ljr;
            uint32_t bd = smbB + (uint32_t)((brow * SAS + k0 + (lj & 1) * 8) * 2);
            ldsm_x4(bfr[nj][0], bfr[nj][1], bfr[nj][2], bfr[nj][3], bd);
        }
#pragma unroll
        for (int mi = 0; mi < 2; mi++)
#pragma unroll
            for (int nj = 0; nj < 4; nj++) {
                mma16816(acc[mi][2 * nj + 0], a[mi][0], a[mi][1], a[mi][2], a[mi][3],
                         bfr[nj][0], bfr[nj][1]);
                mma16816(acc[mi][2 * nj + 1], a[mi][0], a[mi][1], a[mi][2], a[mi][3],
                         bfr[nj][2], bfr[nj][3]);
            }
    }

    // epilogue: s~ = qn - 2*dot + kn ; fp16 store + 64-block min
    int colbase = n0 + warpN * 64;
#pragma unroll
    for (int mi = 0; mi < 2; mi++) {
#pragma unroll
        for (int rr = 0; rr < 2; rr++) {
            int q  = b0q + warpM * 32 + mi * 16 + rr * 8 + (lane >> 2);
            float qn = g_qnorm[q];
            float mn = finf();
            __half* dst = g_sh + (size_t)q * NKP;
#pragma unroll
            for (int ni = 0; ni < 8; ni++) {
                int gn = colbase + ni * 8 + 2 * (lane & 3);
                float d0 = acc[mi][ni][2 * rr + 0];
                float d1 = acc[mi][ni][2 * rr + 1];
                float s0 = (gn     < NK) ? (qn - 2.f * d0 + g_keynorm[gn])     : finf();
                float s1 = (gn + 1 < NK) ? (qn - 2.f * d1 + g_keynorm[gn + 1]) : finf();
                __half h0 = __float2half(s0), h1 = __float2half(s1);
                __half2 p; p.x = h0; p.y = h1;
                *(__half2*)(dst + gn) = p;
                mn = fminf(mn, fminf(__half2float(h0), __half2float(h1)));
            }
#pragma unroll
            for (int s = 1; s < 4; s <<= 1)
                mn = fminf(mn, __shfl_xor_sync(0xffffffffu, mn, s));
            if ((lane & 3) == 0)
                g_bmin[(size_t)q * NBLK + blockIdx.x * 2 + warpN] = mn;
        }
    }
}

// ---------------- K2: select via screen + EXACT frozen-chain rescore --------
__global__ __launch_bounds__(256) void topk_sel(const float* __restrict__ Q,
                                                const float* __restrict__ Kd) {
    int b    = blockIdx.x;
    int tid  = threadIdx.x;
    int w    = tid >> 5;
    int lane = tid & 31;

    __shared__ float smin[256];
    __shared__ float sv[CAP];
    __shared__ int   si[CAP];
    __shared__ float qrow[DIM];
    __shared__ float kbuf[8][DIM];
    __shared__ int   s_cnt;

    const float* bm = g_bmin + (size_t)b * NBLK;

    // ---- pass 1: tau from block minima ----
    float m = finf();
    for (int p = tid; p < NBLK; p += 256) m = fminf(m, bm[p]);
    smin[tid] = m;
    if (tid == 0) s_cnt = 0;
    for (int k = tid; k < DIM; k += 256) qrow[k] = Q[(size_t)b * DIM + k];
    __syncthreads();

    for (int k = 2; k <= 256; k <<= 1) {
        for (int j = k >> 1; j; j >>= 1) {
            int ixj = tid ^ j;
            if (ixj > tid) {
                float v1 = smin[tid], v2 = smin[ixj];
                bool up = ((tid & k) == 0);
                if ((v1 < v2) != up) { smin[tid] = v2; smin[ixj] = v1; }
            }
            __syncthreads();
        }
    }
    float T2 = smin[TOPK - 1] + 2.f * MARG;   // superset threshold
    __syncthreads();

    // ---- pass 2: candidates from fp16 screen matrix (warp per block) ----
    const __half* srow = g_sh + (size_t)b * NKP;
    for (int p = w; p < NBLK; p += 8) {
        if (bm[p] <= T2) {
            int nb = p * 64 + lane * 2;
            __half2 h2 = *(const __half2*)(srow + nb);
            float f0 = __half2float(h2.x);
            float f1 = __half2float(h2.y);
            if (nb < NK && f0 <= T2) {
                int q = atomicAdd(&s_cnt, 1);
                if (q < CAP) si[q] = nb;
            }
            if (nb + 1 < NK && f1 <= T2) {
                int q = atomicAdd(&s_cnt, 1);
                if (q < CAP) si[q] = nb + 1;
            }
        }
    }
    __syncthreads();
    int cnt = s_cnt; if (cnt > CAP) cnt = CAP;

    // ---- exact rescore with the FROZEN chain (warp per candidate) ----
    float qn = g_qnorm[b];
    for (int c = w; c < cnt; c += 8) {
        int n = si[c];
        float4 kv = *(const float4*)(Kd + (size_t)n * DIM + lane * 4);
        *(float4*)&kbuf[w][lane * 4] = kv;
        __syncwarp();
        if (lane == 0) {
            float acc = 0.f;
#pragma unroll
            for (int k = 0; k < DIM; k++)
                acc = fmaf(qrow[k], kbuf[w][k], acc);   // ascending k, FMA — frozen
            sv[c] = __fadd_rn(__fsub_rn(qn, 2.f * acc), g_keynorm[n]);
        }
        __syncwarp();
    }
    __syncthreads();

    int P = 64; while (P < cnt) P <<= 1;
    for (int i = tid; i < P; i += 256)
        if (i >= cnt) { sv[i] = finf(); si[i] = 0x7fffffff; }
    __syncthreads();

    // bitonic sort by (value, index) ascending — canonical, deterministic
    for (int k = 2; k <= P; k <<= 1) {
        for (int j = k >> 1; j; j >>= 1) {
            for (int i = tid; i < P; i += 256) {
                int ixj = i ^ j;
                if (ixj > i) {
                    float v1 = sv[i], v2 = sv[ixj];
                    int  i1 = si[i],  i2 = si[ixj];
                    bool up   = ((i & k) == 0);
                    bool less = (v1 < v2) || (v1 == v2 && i1 < i2);
                    if (less != up) {
                        sv[i] = v2; sv[ixj] = v1;
                        si[i] = i2; si[ixj] = i1;
                    }
                }
            }
            __syncthreads();
        }
    }

    if (tid < TOPK) {
        int ki = si[tid];
        if (ki < 0) ki = 0;
        if (ki >= NK) ki = NK - 1;   // fail-soft: never emit OOB index
        g_topk[b * TOPK + tid] = ki;
    }
}

// ---------------- K3: fp32 recompute (as reference) + weighting (FROZEN) ----
__global__ __launch_bounds__(128) void out_kernel(const float* __restrict__ Q,
                                                  const float* __restrict__ Kd,
                                                  const float* __restrict__ V,
                                                  float* __restrict__ out) {
    int b    = blockIdx.x;
    int lane = threadIdx.x & 31;
    int warp = threadIdx.x >> 5;
    __shared__ float sqd[TOPK];

    const float* qr = Q + (size_t)b * DIM;
    for (int j = warp; j < TOPK; j += 4) {
        int ki = g_topk[b * TOPK + j];
        const float* kr = Kd + (size_t)ki * DIM;
        float acc = 0.f;
#pragma unroll
        for (int m = 0; m < 4; m++) {
            float d = qr[lane + 32 * m] - kr[lane + 32 * m];
            float p = __fmul_rn(d, d);
            acc = __fadd_rn(acc, p);
        }
#pragma unroll
        for (int s = 16; s; s >>= 1) acc += __shfl_xor_sync(0xffffffffu, acc, s);
        if (lane == 0) sqd[j] = acc;
    }
    __syncthreads();

    if (threadIdx.x == 0) {
        float s1 = 0.f, s2 = 0.f;
        for (int j = 0; j < TOPK; j++) {
            float w = 1.f / (sqd[j] + DELTA);
            s1 += w;
            s2 += w * V[g_topk[b * TOPK + j]];
        }
        out[b] = s2 / s1;
    }
}

// ---------------- launch ----------------------------------------------------
extern "C" void kernel_launch(void* const* d_in, const int* in_sizes, int n_in,
                              void* d_out, int out_size) {
    const float* Q  = nullptr;   // 262144 elems
    const float* Kd = nullptr;   // 12800000 elems
    const float* V  = nullptr;   // 100000 elems
    for (int i = 0; i < n_in; i++) {
        if      (in_sizes[i] == BQ * DIM) Q  = (const float*)d_in[i];
        else if (in_sizes[i] == NK * DIM) Kd = (const float*)d_in[i];
        else if (in_sizes[i] == NK)       V  = (const float*)d_in[i];
    }
    float* out = (float*)d_out;
    if (!Q || !Kd || !V) return;

    norms_kernel<<<(NK + 7) / 8, 256>>>(Kd, NK, 0);
    norms_kernel<<<(BQ + 7) / 8, 256>>>(Q,  BQ, 1);

    // bf16 copies (zero-padded keys)
    {
        __nv_bfloat16* qb = nullptr; cudaGetSymbolAddress((void**)&qb, g_Qb);
        __nv_bfloat16* kb = nullptr; cudaGetSymbolAddress((void**)&kb, g_Kb);
        int nq = BQ * DIM;
        int nk = NKP * DIM;
        cvt_bf16<<<(nq / 4 + 255) / 256, 256>>>(Q,  qb, nq,       nq);
        cvt_bf16<<<(nk / 4 + 255) / 256, 256>>>(Kd, kb, NK * DIM, nk);
    }

    static int smem_set = 0;
    if (!smem_set) {
        cudaFuncSetAttribute(screen_gemm, cudaFuncAttributeMaxDynamicSharedMemorySize,
                             SMEM_TOT);
        smem_set = 1;
    }
    dim3 sgrid(NKP / 128, BQ / 128);   // 782 x 16
    screen_gemm<<<sgrid, 256, SMEM_TOT>>>();

    topk_sel<<<BQ, 256>>>(Q, Kd);

    out_kernel<<<BQ, 128>>>(Q, Kd, V, out);
}